// round 1
// baseline (speedup 1.0000x reference)
#include <cuda_runtime.h>
#include <cuda_bf16.h>
#include <math.h>

// Problem constants (fixed by setup_inputs)
#define MAXN 1024
#define MAXK 512
#define MARGIN 1.0f

// Scratch (device globals — no allocation allowed)
__device__ float g_sq[MAXN];                 // squared norms
__device__ float g_dist[MAXN * MAXN];        // pairwise distances
__device__ float g_losses[MAXN];             // per-anchor loss

// ---------------------------------------------------------------------------
// Kernel 1: squared row norms. One warp per row.
// ---------------------------------------------------------------------------
__global__ void norms_kernel(const float* __restrict__ X, int N, int K) {
    int warps_per_block = blockDim.x / 32;
    int row = blockIdx.x * warps_per_block + (threadIdx.x >> 5);
    if (row >= N) return;
    int lane = threadIdx.x & 31;
    const float4* r = (const float4*)(X + (size_t)row * K);
    int K4 = K >> 2;
    float s = 0.f;
    for (int c = lane; c < K4; c += 32) {
        float4 v = r[c];
        s += v.x * v.x + v.y * v.y + v.z * v.z + v.w * v.w;
    }
#pragma unroll
    for (int o = 16; o; o >>= 1) s += __shfl_xor_sync(0xffffffffu, s, o);
    if (lane == 0) g_sq[row] = s;
}

// ---------------------------------------------------------------------------
// Kernel 2: D = sqrt(relu(sq_i + sq_j - 2 * X X^T)), tiled fp32 SGEMM.
// BM=BN=64, BK=16, 256 threads, 4x4 microtile per thread.
// ---------------------------------------------------------------------------
#define BM 64
#define BN 64
#define BK 16
#define SPAD 4   // smem row stride BM+4=68: keeps float4 alignment (68%4==0)

__global__ __launch_bounds__(256) void dist_gemm_kernel(
    const float* __restrict__ X, int N, int K, float* __restrict__ D)
{
    __shared__ float As[BK][BM + SPAD];
    __shared__ float Bs[BK][BN + SPAD];

    const int bm = blockIdx.y * BM;
    const int bn = blockIdx.x * BN;
    const int t  = threadIdx.x;

    // load mapping: 64 rows x 16 cols per tile = 1024 floats = 256 x float4
    const int lr = t >> 2;          // 0..63 row within tile
    const int lc = (t & 3) << 2;    // 0,4,8,12 col group

    // compute mapping: 16x16 grid of 4x4 microtiles
    const int tm = (t >> 4) << 2;   // 0..60
    const int tn = (t & 15) << 2;   // 0..60

    float acc[4][4] = {};

    const float* Arow = X + (size_t)(bm + lr) * K + lc;
    const float* Brow = X + (size_t)(bn + lr) * K + lc;

    for (int k0 = 0; k0 < K; k0 += BK) {
        float4 a = *(const float4*)(Arow + k0);
        float4 b = *(const float4*)(Brow + k0);
        As[lc + 0][lr] = a.x; As[lc + 1][lr] = a.y;
        As[lc + 2][lr] = a.z; As[lc + 3][lr] = a.w;
        Bs[lc + 0][lr] = b.x; Bs[lc + 1][lr] = b.y;
        Bs[lc + 2][lr] = b.z; Bs[lc + 3][lr] = b.w;
        __syncthreads();
#pragma unroll
        for (int k = 0; k < BK; k++) {
            float4 av = *(const float4*)&As[k][tm];
            float4 bv = *(const float4*)&Bs[k][tn];
            float am[4] = {av.x, av.y, av.z, av.w};
            float bm_[4] = {bv.x, bv.y, bv.z, bv.w};
#pragma unroll
            for (int x = 0; x < 4; x++)
#pragma unroll
                for (int y = 0; y < 4; y++)
                    acc[x][y] += am[x] * bm_[y];
        }
        __syncthreads();
    }

    // epilogue: distance transform + store
#pragma unroll
    for (int x = 0; x < 4; x++) {
        int i = bm + tm + x;
        float sqi = g_sq[i];
        float4 o;
        float* op = &o.x;
#pragma unroll
        for (int y = 0; y < 4; y++) {
            int j = bn + tn + y;
            float d2 = sqi + g_sq[j] - 2.0f * acc[x][y];
            d2 = fmaxf(d2, 0.0f);
            op[y] = sqrtf(d2);
        }
        *(float4*)(D + (size_t)i * N + bn + tn) = o;
    }
}

// ---------------------------------------------------------------------------
// Kernel 3: per-anchor triplet loss. One block (256 thr) per anchor.
// loss[i] = sum_{p: lbl[p]==lbl[i]} sum_{k: lbl[k]!=lbl[i]} relu(d[p]-d[k]+m)
// Deterministic: fixed iteration order, fixed tree reduce.
// ---------------------------------------------------------------------------
__global__ __launch_bounds__(256) void anchor_loss_kernel(
    const float* __restrict__ D, const int* __restrict__ labels, int N)
{
    __shared__ float sh_d[MAXN];     // raw distances row
    __shared__ float sh_neg[MAXN];   // dist, or +BIG if positive (relu -> 0)
    __shared__ int   sh_lbl[MAXN];
    __shared__ float red[256];

    const int i = blockIdx.x;
    const int tid = threadIdx.x;
    const int li = labels[i];
    const float* row = D + (size_t)i * N;

    for (int j = tid; j < N; j += 256) {
        float d = row[j];
        int lj = labels[j];
        sh_d[j] = d;
        sh_lbl[j] = lj;
        sh_neg[j] = (lj == li) ? 3.0e30f : d;   // positives never fire relu
    }
    __syncthreads();

    float sum = 0.0f;
    for (int p = 0; p < N; p++) {
        if (sh_lbl[p] != li) continue;          // only positives (incl. diagonal)
        float dp = sh_d[p] + MARGIN;
        for (int k = tid; k < N; k += 256) {
            float t = dp - sh_neg[k];
            sum += fmaxf(t, 0.0f);
        }
    }

    red[tid] = sum;
    __syncthreads();
#pragma unroll
    for (int s = 128; s > 0; s >>= 1) {
        if (tid < s) red[tid] += red[tid + s];
        __syncthreads();
    }
    if (tid == 0) g_losses[i] = red[0];
}

// ---------------------------------------------------------------------------
// Kernel 4: final reduce -> out[0]. Single block, deterministic.
// ---------------------------------------------------------------------------
__global__ __launch_bounds__(256) void final_reduce_kernel(float* __restrict__ out, int N) {
    __shared__ float red[256];
    int tid = threadIdx.x;
    float s = 0.0f;
    for (int j = tid; j < N; j += 256) s += g_losses[j];
    red[tid] = s;
    __syncthreads();
#pragma unroll
    for (int st = 128; st > 0; st >>= 1) {
        if (tid < st) red[tid] += red[tid + st];
        __syncthreads();
    }
    if (tid == 0) out[0] = red[0] / ((float)N + 1e-8f);
}

// ---------------------------------------------------------------------------
extern "C" void kernel_launch(void* const* d_in, const int* in_sizes, int n_in,
                              void* d_out, int out_size)
{
    const float* features = (const float*)d_in[0];
    const int*   labels   = (const int*)d_in[1];
    float*       out      = (float*)d_out;

    const int N = in_sizes[1];            // 1024
    const int K = in_sizes[0] / N;        // 512

    float* D;
    cudaGetSymbolAddress((void**)&D, g_dist);

    // 1. squared norms (8 warps / block)
    norms_kernel<<<(N + 7) / 8, 256>>>(features, N, K);

    // 2. distance matrix
    dim3 grid(N / BN, N / BM);
    dist_gemm_kernel<<<grid, 256>>>(features, N, K, D);

    // 3. per-anchor loss
    anchor_loss_kernel<<<N, 256>>>(D, labels, N);

    // 4. final reduce
    final_reduce_kernel<<<1, 256>>>(out, N);
}

// round 2
// speedup vs baseline: 5.0051x; 5.0051x over previous
#include <cuda_runtime.h>
#include <cuda_bf16.h>
#include <math.h>

#define MAXN 1024
#define MARGIN 1.0f

// Scratch (device globals — allocation is forbidden)
__device__ float g_sq[MAXN];
__device__ float g_dist[MAXN * MAXN];
__device__ float g_losses[MAXN];
__device__ unsigned int g_count;   // zero-initialized; self-resets each launch

// ---------------------------------------------------------------------------
// Kernel 1: squared row norms. One warp per row.
// ---------------------------------------------------------------------------
__global__ void norms_kernel(const float* __restrict__ X, int N, int K) {
    int warps_per_block = blockDim.x / 32;
    int row = blockIdx.x * warps_per_block + (threadIdx.x >> 5);
    if (row >= N) return;
    int lane = threadIdx.x & 31;
    const float4* r = (const float4*)(X + (size_t)row * K);
    int K4 = K >> 2;
    float s = 0.f;
    for (int c = lane; c < K4; c += 32) {
        float4 v = r[c];
        s += v.x * v.x + v.y * v.y + v.z * v.z + v.w * v.w;
    }
#pragma unroll
    for (int o = 16; o; o >>= 1) s += __shfl_xor_sync(0xffffffffu, s, o);
    if (lane == 0) g_sq[row] = s;
}

// ---------------------------------------------------------------------------
// Kernel 2: symmetric distance GEMM. Only upper-triangular 64x64 blocks
// (136 CTAs == one wave on 148 SMs), mirror-write the transpose.
// BM=BN=64, BK=16, 256 threads, 4x4 microtile, double-buffered global loads.
// ---------------------------------------------------------------------------
#define BM 64
#define BN 64
#define BK 16
#define SPAD 4

__global__ __launch_bounds__(256) void dist_gemm_sym_kernel(
    const float* __restrict__ X, int N, int K, float* __restrict__ D)
{
    __shared__ float As[BK][BM + SPAD];
    __shared__ float Bs[BK][BN + SPAD];

    // decode triangular block index: row bi has (nb - bi) blocks
    const int nb = N / BM;
    int rem = blockIdx.x;
    int bi = 0;
    while (rem >= nb - bi) { rem -= nb - bi; bi++; }
    const int bj = bi + rem;
    const int bm = bi * BM;
    const int bn = bj * BN;

    const int t  = threadIdx.x;
    const int lr = t >> 2;          // 0..63
    const int lc = (t & 3) << 2;    // 0,4,8,12
    const int tm = (t >> 4) << 2;   // 0..60
    const int tn = (t & 15) << 2;   // 0..60

    float acc[4][4] = {};

    const float* Arow = X + (size_t)(bm + lr) * K + lc;
    const float* Brow = X + (size_t)(bn + lr) * K + lc;

    float4 a = *(const float4*)(Arow);
    float4 b = *(const float4*)(Brow);

    for (int k0 = 0; k0 < K; k0 += BK) {
        As[lc + 0][lr] = a.x; As[lc + 1][lr] = a.y;
        As[lc + 2][lr] = a.z; As[lc + 3][lr] = a.w;
        Bs[lc + 0][lr] = b.x; Bs[lc + 1][lr] = b.y;
        Bs[lc + 2][lr] = b.z; Bs[lc + 3][lr] = b.w;
        __syncthreads();
        if (k0 + BK < K) {                       // prefetch next tile
            a = *(const float4*)(Arow + k0 + BK);
            b = *(const float4*)(Brow + k0 + BK);
        }
#pragma unroll
        for (int k = 0; k < BK; k++) {
            float4 av = *(const float4*)&As[k][tm];
            float4 bv = *(const float4*)&Bs[k][tn];
            float am[4] = {av.x, av.y, av.z, av.w};
            float bn_[4] = {bv.x, bv.y, bv.z, bv.w};
#pragma unroll
            for (int x = 0; x < 4; x++)
#pragma unroll
                for (int y = 0; y < 4; y++)
                    acc[x][y] += am[x] * bn_[y];
        }
        __syncthreads();
    }

    // epilogue: d = sqrt(relu(sq_i + sq_j - 2 dot)); store block + mirror
#pragma unroll
    for (int x = 0; x < 4; x++) {
        int i = bm + tm + x;
        float sqi = __ldg(&g_sq[i]);
        float4 o;
        float* op = &o.x;
#pragma unroll
        for (int y = 0; y < 4; y++) {
            int j = bn + tn + y;
            float d2 = sqi + __ldg(&g_sq[j]) - 2.0f * acc[x][y];
            op[y] = sqrtf(fmaxf(d2, 0.0f));
        }
        *(float4*)(D + (size_t)i * N + bn + tn) = o;
        if (bi != bj) {
#pragma unroll
            for (int y = 0; y < 4; y++)
                D[(size_t)(bn + tn + y) * N + i] = op[y];
        }
    }
}

// ---------------------------------------------------------------------------
// Kernel 3: per-anchor triplet loss + fused final reduce (last block done).
// One block (256 thr) per anchor.
// ---------------------------------------------------------------------------
__global__ __launch_bounds__(256) void anchor_loss_kernel(
    const float* __restrict__ D, const int* __restrict__ labels, int N,
    float* __restrict__ out)
{
    __shared__ float sh_neg[MAXN];   // dist, or +BIG for positives (relu -> 0)
    __shared__ float sh_pos[MAXN];   // compacted positive distances
    __shared__ int   sh_npos;
    __shared__ float red[256];
    __shared__ int   sh_islast;

    const int i = blockIdx.x;
    const int tid = threadIdx.x;
    const int li = labels[i];
    const float* row = D + (size_t)i * N;

    // classify into neg array (positives neutralized)
    for (int j = tid; j < N; j += 256) {
        float d = __ldg(&row[j]);
        sh_neg[j] = (__ldg(&labels[j]) == li) ? 1.0e30f : d;
    }

    // warp 0: deterministic ballot compaction of positives
    if (tid < 32) {
        int base = 0;
        for (int j0 = 0; j0 < N; j0 += 32) {
            int j = j0 + tid;
            int m = (__ldg(&labels[j]) == li);
            unsigned bal = __ballot_sync(0xffffffffu, m);
            if (m) {
                int pos = base + __popc(bal & ((1u << tid) - 1u));
                sh_pos[pos] = __ldg(&row[j]);
            }
            base += __popc(bal);
        }
        if (tid == 0) sh_npos = base;
    }
    __syncthreads();

    const int npos = sh_npos;
    // register-cache this thread's 4 negatives
    float n0 = sh_neg[tid];
    float n1 = sh_neg[tid + 256];
    float n2 = sh_neg[tid + 512];
    float n3 = sh_neg[tid + 768];

    float sum = 0.0f;
    for (int p = 0; p < npos; p++) {
        float dp = sh_pos[p] + MARGIN;
        sum += fmaxf(dp - n0, 0.0f);
        sum += fmaxf(dp - n1, 0.0f);
        sum += fmaxf(dp - n2, 0.0f);
        sum += fmaxf(dp - n3, 0.0f);
    }

    red[tid] = sum;
    __syncthreads();
#pragma unroll
    for (int s = 128; s > 0; s >>= 1) {
        if (tid < s) red[tid] += red[tid + s];
        __syncthreads();
    }
    if (tid == 0) {
        g_losses[i] = red[0];
        __threadfence();
        unsigned v = atomicAdd(&g_count, 1u);
        sh_islast = (v == (unsigned)(gridDim.x - 1));
    }
    __syncthreads();

    // last finished block performs the deterministic final reduce
    if (sh_islast) {
        float s = 0.0f;
        for (int j = tid; j < N; j += 256) s += g_losses[j];
        red[tid] = s;
        __syncthreads();
#pragma unroll
        for (int st = 128; st > 0; st >>= 1) {
            if (tid < st) red[tid] += red[tid + st];
            __syncthreads();
        }
        if (tid == 0) {
            out[0] = red[0] / ((float)N + 1e-8f);
            g_count = 0u;            // reset for next graph replay
        }
    }
}

// ---------------------------------------------------------------------------
extern "C" void kernel_launch(void* const* d_in, const int* in_sizes, int n_in,
                              void* d_out, int out_size)
{
    const float* features = (const float*)d_in[0];
    const int*   labels   = (const int*)d_in[1];
    float*       out      = (float*)d_out;

    const int N = in_sizes[1];            // 1024
    const int K = in_sizes[0] / N;        // 512

    float* D;
    cudaGetSymbolAddress((void**)&D, g_dist);

    norms_kernel<<<(N + 7) / 8, 256>>>(features, N, K);

    const int nb = N / BM;                // 16
    dist_gemm_sym_kernel<<<nb * (nb + 1) / 2, 256>>>(features, N, K, D);

    anchor_loss_kernel<<<N, 256>>>(D, labels, N, out);
}